// round 10
// baseline (speedup 1.0000x reference)
#include <cuda_runtime.h>
#include <math.h>

// Problem constants
#define NB   64     // batch
#define NL   32     // caption length
#define NT   31     // decode steps = L-1
#define NV   16000  // vocab
#define NE   512    // ENC = DEC = ATT
#define NP   256    // pixels

#define GRIDN 128   // persistent kernel blocks (co-resident, 1 per SM)

// ---------------- device scratch (no allocation allowed) ----------------
__device__ float g_enc [NB * NP * NE];        // [B][P][C]
__device__ float g_att1[NB * NP * NE];        // [B][P][A]
__device__ float g_mean[NB * NE];
__device__ float g_h   [NB * NE];
__device__ float g_c   [NB * NE];
__device__ float g_Hall[NT * NB * NE];        // h2 per step
__device__ float g_xprj[NT * NB * 2048];      // emb gates (INTERLEAVED 4d+g) + biases
__device__ float g_yA  [NB * 1024];           // [y_dec(512) | y_beta(512)] per batch
__device__ float g_gh  [NB * 2048];           // h @ Whh (interleaved 4d+g)
__device__ float g_awe [NB * NE];
__device__ float g_WA  [3072 * 512];          // [Wdec; Wbeta; Whh interleaved 4d+g]
__device__ float g_WCD [2048 * 512];          // Wih[:,256:768] rows interleaved 4d+g
__device__ float g_Wihx[2048 * 256];          // Wih[:,0:256]   rows interleaved 4d+g
__device__ float g_bsum[2048];                // (b_ih+b_hh) interleaved 4d+g
__device__ int   g_capx[2048];                // emb row per (t,b)
__device__ int   g_rowA[2048];                // active row -> t*64+b (into Hall)
__device__ int   g_rowO[2048];                // active row -> b*31+t (into out)
__device__ int   g_nact[1];
__device__ unsigned g_bar[640];               // leaves [i*32] i<16, root [512], rel [576]

__device__ __forceinline__ float sigf(float x) { return 1.0f / (1.0f + expf(-x)); }

// ============================================================================
// High-throughput SGEMM: C[M,N] = A[M,K] * B[N,K]^T (+bias)  (45 TF/s measured)
// ============================================================================
__global__ void __launch_bounds__(256, 2)
sgemm128(const float* __restrict__ A, int lda, const int* __restrict__ arow,
         const float* __restrict__ B, int ldb,
         const float* __restrict__ bias,
         float* __restrict__ C, int ldc, const int* __restrict__ crow,
         int M, const int* __restrict__ Mdev, int K)
{
    int Mv = Mdev ? *Mdev : M;
    int m0 = blockIdx.x * 128;
    if (m0 >= Mv) return;
    int n0 = blockIdx.y * 128;

    __shared__ float As[2][8][128];
    __shared__ float Bs[2][8][128];

    int tid = threadIdx.x;
    int lrow = tid >> 1;
    int lk4  = (tid & 1) * 4;

    int rowm = m0 + lrow;
    int ca   = (rowm < Mv) ? rowm : (Mv - 1);
    int ar   = arow ? arow[ca] : ca;
    const float* Ap = A + (long long)ar * lda + lk4;
    const float* Bp = B + (long long)(n0 + lrow) * ldb + lk4;

    int tx = tid & 15;
    int ty = tid >> 4;

    float acc[8][8];
#pragma unroll
    for (int i = 0; i < 8; i++)
#pragma unroll
        for (int j = 0; j < 8; j++) acc[i][j] = 0.0f;

    {
        float4 a4 = *(const float4*)Ap;
        float4 b4 = *(const float4*)Bp;
        As[0][lk4 + 0][lrow] = a4.x; As[0][lk4 + 1][lrow] = a4.y;
        As[0][lk4 + 2][lrow] = a4.z; As[0][lk4 + 3][lrow] = a4.w;
        Bs[0][lk4 + 0][lrow] = b4.x; Bs[0][lk4 + 1][lrow] = b4.y;
        Bs[0][lk4 + 2][lrow] = b4.z; Bs[0][lk4 + 3][lrow] = b4.w;
    }
    __syncthreads();

    int ntiles = K >> 3;
    int buf = 0;
    for (int t = 0; t < ntiles; t++) {
        float4 na, nb;
        bool more = (t + 1 < ntiles);
        if (more) {
            int kk = (t + 1) << 3;
            na = *(const float4*)(Ap + kk);
            nb = *(const float4*)(Bp + kk);
        }
#pragma unroll
        for (int k = 0; k < 8; k++) {
            float a[8], b[8];
            *(float4*)(a)     = *(const float4*)&As[buf][k][ty * 4];
            *(float4*)(a + 4) = *(const float4*)&As[buf][k][64 + ty * 4];
            *(float4*)(b)     = *(const float4*)&Bs[buf][k][tx * 4];
            *(float4*)(b + 4) = *(const float4*)&Bs[buf][k][64 + tx * 4];
#pragma unroll
            for (int i = 0; i < 8; i++)
#pragma unroll
                for (int j = 0; j < 8; j++)
                    acc[i][j] = fmaf(a[i], b[j], acc[i][j]);
        }
        if (more) {
            int nbuf = buf ^ 1;
            As[nbuf][lk4 + 0][lrow] = na.x; As[nbuf][lk4 + 1][lrow] = na.y;
            As[nbuf][lk4 + 2][lrow] = na.z; As[nbuf][lk4 + 3][lrow] = na.w;
            Bs[nbuf][lk4 + 0][lrow] = nb.x; Bs[nbuf][lk4 + 1][lrow] = nb.y;
            Bs[nbuf][lk4 + 2][lrow] = nb.z; Bs[nbuf][lk4 + 3][lrow] = nb.w;
            __syncthreads();
            buf = nbuf;
        }
    }

    float bv[8];
#pragma unroll
    for (int jh = 0; jh < 2; jh++)
#pragma unroll
        for (int j = 0; j < 4; j++)
            bv[jh * 4 + j] = bias ? bias[n0 + jh * 64 + tx * 4 + j] : 0.0f;

#pragma unroll
    for (int i = 0; i < 8; i++) {
        int r = m0 + ((i < 4) ? (ty * 4 + i) : (64 + ty * 4 + i - 4));
        if (r >= Mv) continue;
        int cr = crow ? crow[r] : r;
        float* Cp = C + (long long)cr * ldc + n0;
#pragma unroll
        for (int jh = 0; jh < 2; jh++) {
            float4 v;
            v.x = acc[i][jh * 4 + 0] + bv[jh * 4 + 0];
            v.y = acc[i][jh * 4 + 1] + bv[jh * 4 + 1];
            v.z = acc[i][jh * 4 + 2] + bv[jh * 4 + 2];
            v.w = acc[i][jh * 4 + 3] + bv[jh * 4 + 3];
            *(float4*)(Cp + jh * 64 + tx * 4) = v;
        }
    }
}

// ---------------- small tiled SGEMM (h0/c0 only) ----------------------------
__global__ void sgemm64(const float* __restrict__ A, int lda,
                        const float* __restrict__ B, int ldb,
                        const float* __restrict__ bias,
                        float* __restrict__ C, int ldc, int K)
{
    int n0 = blockIdx.y * 64;
    __shared__ float As[16][68];
    __shared__ float Bs[16][68];

    int tid = threadIdx.x;
    int tx = tid & 15, ty = tid >> 4;
    int lm = tid >> 2, lk = (tid & 3) * 4;

    const float* Arow = A + (long long)lm * lda;
    const float* Brow = B + (long long)(n0 + lm) * ldb;

    float acc[4][4];
#pragma unroll
    for (int i = 0; i < 4; i++)
#pragma unroll
        for (int j = 0; j < 4; j++) acc[i][j] = 0.0f;

    for (int kk = 0; kk < K; kk += 16) {
        float4 av = *(const float4*)(Arow + kk + lk);
        float4 bv = *(const float4*)(Brow + kk + lk);
        __syncthreads();
        As[lk + 0][lm] = av.x; As[lk + 1][lm] = av.y;
        As[lk + 2][lm] = av.z; As[lk + 3][lm] = av.w;
        Bs[lk + 0][lm] = bv.x; Bs[lk + 1][lm] = bv.y;
        Bs[lk + 2][lm] = bv.z; Bs[lk + 3][lm] = bv.w;
        __syncthreads();
#pragma unroll
        for (int k = 0; k < 16; k++) {
            float4 a4 = *(const float4*)&As[k][ty * 4];
            float4 b4 = *(const float4*)&Bs[k][tx * 4];
            float aa[4] = {a4.x, a4.y, a4.z, a4.w};
            float bb[4] = {b4.x, b4.y, b4.z, b4.w};
#pragma unroll
            for (int i = 0; i < 4; i++)
#pragma unroll
                for (int j = 0; j < 4; j++) acc[i][j] = fmaf(aa[i], bb[j], acc[i][j]);
        }
    }

#pragma unroll
    for (int i = 0; i < 4; i++) {
        float* Cp = C + (long long)(ty * 4 + i) * ldc + n0 + tx * 4;
#pragma unroll
        for (int j = 0; j < 4; j++)
            Cp[j] = acc[i][j] + bias[n0 + tx * 4 + j];
    }
}

// ---------------- transpose encoder_out [B][C][P] -> enc [B][P][C] ----------
__global__ void transpose_enc(const float* __restrict__ eo, float* __restrict__ enc)
{
    __shared__ float t[32][33];
    int b = blockIdx.z;
    int c0 = blockIdx.x * 32, p0 = blockIdx.y * 32;
    int x = threadIdx.x, y = threadIdx.y;
    for (int i = y; i < 32; i += 8)
        t[i][x] = eo[((long long)b * NE + c0 + i) * NP + p0 + x];
    __syncthreads();
    for (int i = y; i < 32; i += 8)
        enc[((long long)b * NP + p0 + i) * NE + c0 + x] = t[x][i];
}

// ---------------- mean over pixels ------------------------------------------
__global__ void mean_kernel(const float* __restrict__ eo, float* __restrict__ mean)
{
    int row = blockIdx.x * 8 + threadIdx.y;
    int lane = threadIdx.x;
    const float* src = eo + (long long)row * NP;
    float s = 0.0f;
    for (int p = lane; p < NP; p += 32) s += src[p];
#pragma unroll
    for (int o = 16; o > 0; o >>= 1) s += __shfl_xor_sync(0xffffffffu, s, o);
    if (lane == 0) mean[row] = s * (1.0f / NP);
}

// ---------------- setup (also resets barrier state every replay) ------------
__global__ void setup_kernel(const int* __restrict__ caps, const int* __restrict__ lens,
                             const float* __restrict__ b_ih, const float* __restrict__ b_hh)
{
    int tid = threadIdx.x;
    for (int j = tid; j < 2048; j += 256) {
        int d = j >> 2, g = j & 3;                 // interleaved 4d+g
        g_bsum[j] = b_ih[g * 512 + d] + b_hh[g * 512 + d];
    }
    for (int i = tid; i < NT * NB; i += 256) {
        int t = i / NB, b = i % NB;
        g_capx[i] = caps[b * NL + t];
    }
    for (int j = tid; j < 640; j += 256) g_bar[j] = 0;
    __syncthreads();
    if (tid == 0) {
        int cnt = 0;
        for (int t = 0; t < NT; t++)
            for (int b = 0; b < NB; b++)
                if (t < lens[b] - 1) { g_rowA[cnt] = t * NB + b; g_rowO[cnt] = b * NT + t; cnt++; }
        g_nact[0] = cnt;
        for (int i = cnt; i < 2048; i++) { g_rowA[i] = 0; g_rowO[i] = 0; }
    }
}

// ---------------- build stacked/interleaved weights -------------------------
__global__ void wcat_kernel(const float* __restrict__ Wd, const float* __restrict__ Wb,
                            const float* __restrict__ Whh, const float* __restrict__ Wih)
{
    int f4 = blockIdx.x * blockDim.x + threadIdx.x;
    if (f4 < 3072 * 128) {
        int n = f4 >> 7, q = (f4 & 127) * 4;
        const float* src;
        if (n < 512)       src = Wd + n * 512 + q;
        else if (n < 1024) src = Wb + (n - 512) * 512 + q;
        else {
            int m = n - 1024, d = m >> 2, g = m & 3;
            src = Whh + (g * 512 + d) * 512 + q;
        }
        *(float4*)(g_WA + f4 * 4) = *(const float4*)src;
    } else if (f4 < 3072 * 128 + 2048 * 128) {
        int r = f4 - 3072 * 128;
        int n = r >> 7, q = (r & 127) * 4;
        int d = n >> 2, g = n & 3;
        *(float4*)(g_WCD + r * 4) = *(const float4*)(Wih + (g * 512 + d) * 768 + 256 + q);
    } else {
        int r = f4 - 3072 * 128 - 2048 * 128;
        if (r >= 2048 * 64) return;
        int n = r >> 6, q = (r & 63) * 4;
        int d = n >> 2, g = n & 3;
        *(float4*)(g_Wihx + r * 4) = *(const float4*)(Wih + (g * 512 + d) * 768 + q);
    }
}

// ============================================================================
// PERSISTENT RECURRENCE — 3 barrier-epochs/step, attention || h@Whh overlap.
// Tree arrival: 16 leaves (128B apart, 8 arrivals) -> root (16) -> release.
// ============================================================================
__device__ __forceinline__ void gbar_arrive(unsigned target)
{
    __syncthreads();
    if (threadIdx.x == 0) {
        unsigned* leaf = &g_bar[(blockIdx.x & 15) * 32];
        unsigned p;
        asm volatile("atom.acq_rel.gpu.add.u32 %0, [%1], %2;"
                     : "=r"(p) : "l"(leaf), "r"(1u) : "memory");
        if (p == target * 8u - 1u) {
            unsigned q;
            asm volatile("atom.acq_rel.gpu.add.u32 %0, [%1], %2;"
                         : "=r"(q) : "l"(&g_bar[512]), "r"(1u) : "memory");
            if (q == target * 16u - 1u) {
                asm volatile("st.release.gpu.u32 [%0], %1;"
                             :: "l"(&g_bar[576]), "r"(target) : "memory");
            }
        }
    }
}

__device__ __forceinline__ void gbar_wait(unsigned target)
{
    if (threadIdx.x == 0) {
        unsigned v;
        while (true) {
            asm volatile("ld.acquire.gpu.u32 %0, [%1];"
                         : "=r"(v) : "l"(&g_bar[576]) : "memory");
            if (v >= target) break;
            __nanosleep(64);
        }
    }
    __syncthreads();
}

__global__ void __launch_bounds__(256, 1)
recurrence_kernel(const float* __restrict__ eo,
                  const float* __restrict__ b_dec_att,
                  const float* __restrict__ w_full,
                  const float* __restrict__ b_full,
                  const float* __restrict__ b_beta)
{
    __shared__ float sh[9984];                 // ~40KB, re-partitioned per phase
    int blk = blockIdx.x;
    int tid = threadIdx.x;

    for (int t = 0; t < NT; t++) {
        unsigned base = (unsigned)(t * 3);

        // ===== Phase yA (ALL blocks): y[:,blk*8..+7] = h @ WA[blk*8..+7]^T ======
        // in-block split-K x4: group g=tid>>6 handles k in [g*128, g*128+128)
        {
            float (*As)[16][68] = (float(*)[16][68])sh;           // [4][16][68]
            float (*Ws)[16][8]  = (float(*)[16][8])(sh + 4352);   // [4][16][8]
            float* red          = sh + 4864;                      // [4*512]
            int g = tid >> 6, l = tid & 63;
            int bi = l & 15, ci = l >> 4;       // b0 = bi*4, cols c0=ci*2..+1
            int b0 = bi * 4, c0 = ci * 2;
            int k0 = g * 128;
            int wcol = l >> 3, wk = (l & 7) * 2;
            const float* Wb8 = g_WA + (long long)blk * 8 * 512 + k0;

            float acc[4][2];
#pragma unroll
            for (int i = 0; i < 4; i++) { acc[i][0] = 0.0f; acc[i][1] = 0.0f; }

            for (int kk = 0; kk < 128; kk += 16) {
                float4 hv = __ldcg((const float4*)(g_h + l * 512 + k0 + kk + ((l >> 4) & 0)));
                // each thread loads h[row=l][k0+kk .. +16) : 4 float4
                float4 h0 = __ldcg((const float4*)(g_h + l * 512 + k0 + kk + 0));
                float4 h1 = __ldcg((const float4*)(g_h + l * 512 + k0 + kk + 4));
                float4 h2 = __ldcg((const float4*)(g_h + l * 512 + k0 + kk + 8));
                float4 h3 = __ldcg((const float4*)(g_h + l * 512 + k0 + kk + 12));
                float2 wv = *(const float2*)(Wb8 + (long long)wcol * 512 + kk + wk);
                (void)hv;
                __syncthreads();
                As[g][kk ? 0 : 0][0] = As[g][0][0];  // no-op keep structure
                {
                    float* dstc = &As[g][0][l];
                    dstc[0 * 68] = h0.x; dstc[1 * 68] = h0.y; dstc[2 * 68] = h0.z; dstc[3 * 68] = h0.w;
                    dstc[4 * 68] = h1.x; dstc[5 * 68] = h1.y; dstc[6 * 68] = h1.z; dstc[7 * 68] = h1.w;
                    dstc[8 * 68] = h2.x; dstc[9 * 68] = h2.y; dstc[10 * 68] = h2.z; dstc[11 * 68] = h2.w;
                    dstc[12 * 68] = h3.x; dstc[13 * 68] = h3.y; dstc[14 * 68] = h3.z; dstc[15 * 68] = h3.w;
                }
                Ws[g][wk + 0][wcol] = wv.x;
                Ws[g][wk + 1][wcol] = wv.y;
                __syncthreads();
#pragma unroll
                for (int k = 0; k < 16; k++) {
                    float a[4];
                    *(float4*)a = *(const float4*)&As[g][k][b0];
                    float w0 = Ws[g][k][c0], w1 = Ws[g][k][c0 + 1];
#pragma unroll
                    for (int i = 0; i < 4; i++) {
                        acc[i][0] = fmaf(a[i], w0, acc[i][0]);
                        acc[i][1] = fmaf(a[i], w1, acc[i][1]);
                    }
                }
                __syncthreads();
            }
#pragma unroll
            for (int i = 0; i < 4; i++) {
                red[g * 512 + (b0 + i) * 8 + c0 + 0] = acc[i][0];
                red[g * 512 + (b0 + i) * 8 + c0 + 1] = acc[i][1];
            }
            __syncthreads();
            {
                int idx = tid * 2;
#pragma unroll
                for (int r = 0; r < 2; r++, idx++) {
                    int b = idx >> 3, c = idx & 7;
                    float v = red[idx] + red[512 + idx] + red[1024 + idx] + red[1536 + idx];
                    __stcg(&g_yA[b * 1024 + blk * 8 + c], v);
                }
            }
        }
        gbar_arrive(base + 1);

        if (blk < NB) {
            // ===== Attention block (b = blk): wait yA, full attention in-block ==
            gbar_wait(base + 1);
            int b = blk;
            float* att2_s  = sh;            // 512
            float* w_s     = sh + 512;      // 512
            float* red_s   = sh + 1024;     // 256
            float* alpha_s = sh + 1280;     // 256

            for (int a = tid; a < 512; a += 256) {
                att2_s[a] = __ldcg(&g_yA[b * 1024 + a]) + b_dec_att[a];
                w_s[a] = w_full[a];
            }
            __syncthreads();

            const float* arow = g_att1 + ((long long)b * NP + tid) * NE;
            float acc = 0.0f;
#pragma unroll 4
            for (int a = 0; a < 512; a += 4) {
                float4 v4 = *(const float4*)(arow + a);
                acc = fmaf(fmaxf(v4.x + att2_s[a + 0], 0.0f), w_s[a + 0], acc);
                acc = fmaf(fmaxf(v4.y + att2_s[a + 1], 0.0f), w_s[a + 1], acc);
                acc = fmaf(fmaxf(v4.z + att2_s[a + 2], 0.0f), w_s[a + 2], acc);
                acc = fmaf(fmaxf(v4.w + att2_s[a + 3], 0.0f), w_s[a + 3], acc);
            }
            acc += b_full[0];

            red_s[tid] = acc; __syncthreads();
            for (int s = 128; s > 0; s >>= 1) {
                if (tid < s) red_s[tid] = fmaxf(red_s[tid], red_s[tid + s]);
                __syncthreads();
            }
            float mx = red_s[0]; __syncthreads();
            float ex = expf(acc - mx);
            red_s[tid] = ex; __syncthreads();
            for (int s = 128; s > 0; s >>= 1) {
                if (tid < s) red_s[tid] += red_s[tid + s];
                __syncthreads();
            }
            alpha_s[tid] = ex / red_s[0];
            __syncthreads();

            for (int c = tid; c < 512; c += 256) {
                const float* erow = eo + ((long long)b * NE + c) * NP;
                float s = 0.0f;
#pragma unroll 4
                for (int p = 0; p < NP; p += 4) {
                    float4 e4 = *(const float4*)(erow + p);
                    s = fmaf(e4.x, alpha_s[p + 0], s);
                    s = fmaf(e4.y, alpha_s[p + 1], s);
                    s = fmaf(e4.z, alpha_s[p + 2], s);
                    s = fmaf(e4.w, alpha_s[p + 3], s);
                }
                float gpre = __ldcg(&g_yA[b * 1024 + 512 + c]) + b_beta[c];
                __stcg(&g_awe[b * NE + c], sigf(gpre) * s);
            }
            gbar_arrive(base + 2);
        } else {
            // ===== GEMM block: gh[:, gb*32..+31] = h @ Whh-int^T (overlapped) ===
            int gb = blk - NB;                  // 0..63
            float (*As)[16][68] = (float(*)[16][68])sh;            // [2][16][68]
            float (*Ws)[16][36] = (float(*)[16][36])(sh + 2176);   // [2][16][36]
            float* red          = sh + 3328;                       // [2*2048]
            int g = tid >> 7, l = tid & 127;    // k in [g*256, +256)
            int bi = l & 15, ci = l >> 4;       // b0 = bi*4, c0 = ci*4 (8 groups x4)
            int b0 = bi * 4, c0 = ci * 4;
            int k0 = g * 256;
            int arow = l & 63, ahalf = l >> 6;  // h loader
            int wcol = l >> 2, wk = (l & 3) * 4;
            const float* Wg = g_WA + (long long)(1024 + gb * 32) * 512 + k0;

            float acc[4][4];
#pragma unroll
            for (int i = 0; i < 4; i++)
#pragma unroll
                for (int j = 0; j < 4; j++) acc[i][j] = 0.0f;

            for (int kk = 0; kk < 256; kk += 16) {
                int ks = ahalf * 8;
                float4 hA = __ldcg((const float4*)(g_h + arow * 512 + k0 + kk + ks));
                float4 hB = __ldcg((const float4*)(g_h + arow * 512 + k0 + kk + ks + 4));
                float4 wv = *(const float4*)(Wg + (long long)wcol * 512 + kk + wk);
                __syncthreads();
                {
                    float* dstc = &As[g][0][arow];
                    dstc[(ks + 0) * 68] = hA.x; dstc[(ks + 1) * 68] = hA.y;
                    dstc[(ks + 2) * 68] = hA.z; dstc[(ks + 3) * 68] = hA.w;
                    dstc[(ks + 4) * 68] = hB.x; dstc[(ks + 5) * 68] = hB.y;
                    dstc[(ks + 6) * 68] = hB.z; dstc[(ks + 7) * 68] = hB.w;
                }
                Ws[g][wk + 0][wcol] = wv.x; Ws[g][wk + 1][wcol] = wv.y;
                Ws[g][wk + 2][wcol] = wv.z; Ws[g][wk + 3][wcol] = wv.w;
                __syncthreads();
#pragma unroll
                for (int k = 0; k < 16; k++) {
                    float a[4], w[4];
                    *(float4*)a = *(const float4*)&As[g][k][b0];
                    *(float4*)w = *(const float4*)&Ws[g][k][c0];
#pragma unroll
                    for (int i = 0; i < 4; i++)
#pragma unroll
                        for (int j = 0; j < 4; j++)
                            acc[i][j] = fmaf(a[i], w[j], acc[i][j]);
                }
                __syncthreads();
            }
#pragma unroll
            for (int i = 0; i < 4; i++)
#pragma unroll
                for (int j = 0; j < 4; j++)
                    red[g * 2048 + (b0 + i) * 32 + c0 + j] = acc[i][j];
            __syncthreads();
            {
#pragma unroll
                for (int r = 0; r < 8; r++) {
                    int idx = tid * 8 + r;
                    int b = idx >> 5, c = idx & 31;
                    __stcg(&g_gh[b * 2048 + gb * 32 + c], red[idx] + red[2048 + idx]);
                }
            }
            gbar_arrive(base + 2);
        }
        gbar_wait(base + 2);

        // ===== Phase C+D (ALL blocks): gates cols blk*16..+15 (+gh+xprj) + LSTM =
        {
            float (*As)[16][68] = (float(*)[16][68])sh;            // [4][16][68] awe
            float (*Ws)[16][20] = (float(*)[16][20])(sh + 4352);   // [4][16][20]
            float* red          = sh + 5632;                       // [4*1024]
            int g = tid >> 6, l = tid & 63;     // k in [g*128,+128)
            int bi = l & 15, ci = l >> 4;       // b0=bi*4, c0=ci*4
            int b0 = bi * 4, c0 = ci * 4;
            int k0 = g * 128;
            int wcol = l >> 2, wk = (l & 3) * 4;
            const float* Wc = g_WCD + (long long)blk * 16 * 512 + k0;

            float acc[4][4];
#pragma unroll
            for (int i = 0; i < 4; i++)
#pragma unroll
                for (int j = 0; j < 4; j++) acc[i][j] = 0.0f;

            for (int kk = 0; kk < 128; kk += 16) {
                float4 a0 = __ldcg((const float4*)(g_awe + l * 512 + k0 + kk + 0));
                float4 a1 = __ldcg((const float4*)(g_awe + l * 512 + k0 + kk + 4));
                float4 a2 = __ldcg((const float4*)(g_awe + l * 512 + k0 + kk + 8));
                float4 a3 = __ldcg((const float4*)(g_awe + l * 512 + k0 + kk + 12));
                float4 wv = *(const float4*)(Wc + (long long)wcol * 512 + kk + wk);
                __syncthreads();
                {
                    float* dstc = &As[g][0][l];
                    dstc[0 * 68] = a0.x; dstc[1 * 68] = a0.y; dstc[2 * 68] = a0.z; dstc[3 * 68] = a0.w;
                    dstc[4 * 68] = a1.x; dstc[5 * 68] = a1.y; dstc[6 * 68] = a1.z; dstc[7 * 68] = a1.w;
                    dstc[8 * 68] = a2.x; dstc[9 * 68] = a2.y; dstc[10 * 68] = a2.z; dstc[11 * 68] = a2.w;
                    dstc[12 * 68] = a3.x; dstc[13 * 68] = a3.y; dstc[14 * 68] = a3.z; dstc[15 * 68] = a3.w;
                }
                Ws[g][wk + 0][wcol] = wv.x; Ws[g][wk + 1][wcol] = wv.y;
                Ws[g][wk + 2][wcol] = wv.z; Ws[g][wk + 3][wcol] = wv.w;
                __syncthreads();
#pragma unroll
                for (int k = 0; k < 16; k++) {
                    float a[4], w[4];
                    *(float4*)a = *(const float4*)&As[g][k][b0];
                    *(float4*)w = *(const float4*)&Ws[g][k][c0];
#pragma unroll
                    for (int i = 0; i < 4; i++)
#pragma unroll
                        for (int j = 0; j < 4; j++)
                            acc[i][j] = fmaf(a[i], w[j], acc[i][j]);
                }
                __syncthreads();
            }
#pragma unroll
            for (int i = 0; i < 4; i++)
#pragma unroll
                for (int j = 0; j < 4; j++)
                    red[g * 1024 + (b0 + i) * 16 + c0 + j] = acc[i][j];
            __syncthreads();
            {
                int b = tid >> 2, dl = tid & 3;
                int ib = b * 16 + dl * 4;
                float gi = red[ib + 0] + red[1024 + ib + 0] + red[2048 + ib + 0] + red[3072 + ib + 0];
                float gf = red[ib + 1] + red[1024 + ib + 1] + red[2048 + ib + 1] + red[3072 + ib + 1];
                float gg = red[ib + 2] + red[1024 + ib + 2] + red[2048 + ib + 2] + red[3072 + ib + 2];
                float go = red[ib + 3] + red[1024 + ib + 3] + red[2048 + ib + 3] + red[3072 + ib + 3];
                float4 ghv = __ldcg((const float4*)(g_gh + b * 2048 + blk * 16 + dl * 4));
                const float* xp = g_xprj + ((long long)t * NB + b) * 2048 + blk * 16 + dl * 4;
                gi += ghv.x + xp[0];
                gf += ghv.y + xp[1];
                gg += ghv.z + xp[2];
                go += ghv.w + xp[3];
                int d = blk * 4 + dl;
                float cp = g_c[b * NE + d];          // block-private (same SM every step)
                float cn = sigf(gf) * cp + sigf(gi) * tanhf(gg);
                float hn = sigf(go) * tanhf(cn);
                g_c[b * NE + d] = cn;
                __stcg(&g_h[b * NE + d], hn);
                g_Hall[((long long)t * NB + b) * NE + d] = hn;
            }
        }
        gbar_arrive(base + 3);
        gbar_wait(base + 3);
    }
}

// ---------------- host launch -----------------------------------------------
extern "C" void kernel_launch(void* const* d_in, const int* in_sizes, int n_in,
                              void* d_out, int out_size)
{
    const float* eo        = (const float*)d_in[0];
    const int*   caps      = (const int*)  d_in[1];
    const int*   lens      = (const int*)  d_in[2];
    const float* W_enc_att = (const float*)d_in[3];
    const float* b_enc_att = (const float*)d_in[4];
    const float* W_dec_att = (const float*)d_in[5];
    const float* b_dec_att = (const float*)d_in[6];
    const float* w_full    = (const float*)d_in[7];
    const float* b_full    = (const float*)d_in[8];
    const float* emb       = (const float*)d_in[9];
    const float* W_ih      = (const float*)d_in[10];
    const float* W_hh      = (const float*)d_in[11];
    const float* b_ih      = (const float*)d_in[12];
    const float* b_hh      = (const float*)d_in[13];
    const float* W_init_h  = (const float*)d_in[14];
    const float* b_init_h  = (const float*)d_in[15];
    const float* W_init_c  = (const float*)d_in[16];
    const float* b_init_c  = (const float*)d_in[17];
    const float* W_beta    = (const float*)d_in[18];
    const float* b_beta    = (const float*)d_in[19];
    const float* W_fc      = (const float*)d_in[20];
    const float* b_fc      = (const float*)d_in[21];
    float* out = (float*)d_out;

    float *enc, *att1, *mean, *h, *c, *Hall, *xprj, *bsum, *Wihx;
    int *capx, *rowA, *rowO, *nact;
    cudaGetSymbolAddress((void**)&enc,  g_enc);
    cudaGetSymbolAddress((void**)&att1, g_att1);
    cudaGetSymbolAddress((void**)&mean, g_mean);
    cudaGetSymbolAddress((void**)&h,    g_h);
    cudaGetSymbolAddress((void**)&c,    g_c);
    cudaGetSymbolAddress((void**)&Hall, g_Hall);
    cudaGetSymbolAddress((void**)&xprj, g_xprj);
    cudaGetSymbolAddress((void**)&bsum, g_bsum);
    cudaGetSymbolAddress((void**)&Wihx, g_Wihx);
    cudaGetSymbolAddress((void**)&capx, g_capx);
    cudaGetSymbolAddress((void**)&rowA, g_rowA);
    cudaGetSymbolAddress((void**)&rowO, g_rowO);
    cudaGetSymbolAddress((void**)&nact, g_nact);

    cudaMemsetAsync(out, 0, (size_t)out_size * sizeof(float));

    transpose_enc<<<dim3(16, 8, 64), dim3(32, 8)>>>(eo, enc);
    mean_kernel<<<4096, dim3(32, 8)>>>(eo, mean);
    setup_kernel<<<1, 256>>>(caps, lens, b_ih, b_hh);    // also resets g_bar

    // att1 = enc @ W_enc_att^T + b   (M=16384, N=512, K=512)
    sgemm128<<<dim3(128, 4), 256>>>(enc, 512, nullptr, W_enc_att, 512, b_enc_att,
                                    att1, 512, nullptr, NB * NP, nullptr, 512);

    wcat_kernel<<<3072, 256>>>(W_dec_att, W_beta, W_hh, W_ih);

    sgemm64<<<dim3(1, 8), 256>>>(mean, 512, W_init_h, 512, b_init_h, h, 512, 512);
    sgemm64<<<dim3(1, 8), 256>>>(mean, 512, W_init_c, 512, b_init_c, c, 512, 512);

    // x_proj = emb[cap] @ Wihx^T + bsum (interleaved), K=256
    sgemm128<<<dim3(16, 16), 256>>>(emb, 256, capx, Wihx, 256, bsum,
                                    xprj, 2048, nullptr, NT * NB, nullptr, 256);

    // fused 31-step recurrence (persistent, 3 barrier-epochs, attn||gh overlap)
    recurrence_kernel<<<GRIDN, 256>>>(eo, b_dec_att, w_full, b_full, b_beta);

    // Final FC over compacted active rows
    sgemm128<<<dim3(16, 125), 256>>>(Hall, 512, rowA, W_fc, 512, b_fc,
                                     out, NV, rowO, NT * NB, nact, 512);
}